// round 13
// baseline (speedup 1.0000x reference)
#include <cuda_runtime.h>
#include <cuda_bf16.h>
#include <cstdint>
#include <cstddef>

#define N_ROWS 16384
#define M_COLS 4096
#define D_DIM  512

// Static device scratch (allocation-free rule).
__device__ float g_xsq[N_ROWS];
__device__ float g_ssq[M_COLS];
__device__ __nv_bfloat16 g_Xb[N_ROWS * D_DIM];   // 16 MB
__device__ __nv_bfloat16 g_Sb[M_COLS * D_DIM];   // 4 MB

__device__ __forceinline__ uint32_t smem_u32(const void* p) {
    uint32_t a;
    asm("{ .reg .u64 t; cvta.to.shared.u64 t, %1; cvt.u32.u64 %0, t; }" : "=r"(a) : "l"(p));
    return a;
}
#define SW128(o) ((o) ^ (((o) >> 3) & 0x70))

__device__ __forceinline__ void ldmatrix_x4(uint32_t* r, uint32_t addr) {
    asm volatile("ldmatrix.sync.aligned.m8n8.x4.shared.b16 {%0,%1,%2,%3}, [%4];"
                 : "=r"(r[0]), "=r"(r[1]), "=r"(r[2]), "=r"(r[3]) : "r"(addr));
}
__device__ __forceinline__ void mma16816(float* d, const uint32_t* a, uint32_t b0, uint32_t b1) {
    asm volatile("mma.sync.aligned.m16n8k16.row.col.f32.bf16.bf16.f32 "
                 "{%0,%1,%2,%3}, {%4,%5,%6,%7}, {%8,%9}, {%0,%1,%2,%3};"
                 : "+f"(d[0]), "+f"(d[1]), "+f"(d[2]), "+f"(d[3])
                 : "r"(a[0]), "r"(a[1]), "r"(a[2]), "r"(a[3]), "r"(b0), "r"(b1));
}
__device__ __forceinline__ void cp_async16(uint32_t saddr, const void* gaddr) {
    asm volatile("cp.async.cg.shared.global [%0], [%1], 16;" :: "r"(saddr), "l"(gaddr));
}
#define CP_COMMIT()  asm volatile("cp.async.commit_group;" ::: "memory")
#define CP_WAIT(n)   asm volatile("cp.async.wait_group %0;" :: "n"(n) : "memory")

// Dynamic SMEM layout (bytes)
#define OFF_X  0        // 8 chunks of 128x64 bf16, SW128 (16 KB each) = 128 KB
#define OFF_S  131072   // 2 S buffers of 256x64 bf16 (32 KB each) = 64 KB
#define OFF_Q  196608   // ssq[4096] f32 = 16 KB
#define OFF_A  212992   // alphas[4096] f32 = 16 KB
#define OFF_R  229376   // red: 128 rows x 4 warpN x f32 = 2 KB
#define SMEM_TOTAL 231424

// ---------------- prep: fp32 -> bf16 + row norms (one warp per row) ----------------
__global__ void prep_kernel(const float* __restrict__ A, int rows, int which) {
    int w = (blockIdx.x * blockDim.x + threadIdx.x) >> 5;
    int lane = threadIdx.x & 31;
    if (w >= rows) return;
    const float4* a = reinterpret_cast<const float4*>(A + (size_t)w * D_DIM);
    __nv_bfloat162* dst = reinterpret_cast<__nv_bfloat162*>((which ? g_Sb : g_Xb) + (size_t)w * D_DIM);
    float s = 0.f;
    #pragma unroll 4
    for (int i = lane; i < D_DIM / 4; i += 32) {
        float4 v = a[i];
        dst[2 * i]     = __floats2bfloat162_rn(v.x, v.y);
        dst[2 * i + 1] = __floats2bfloat162_rn(v.z, v.w);
        s = fmaf(v.x, v.x, s); s = fmaf(v.y, v.y, s);
        s = fmaf(v.z, v.z, s); s = fmaf(v.w, v.w, s);
    }
    #pragma unroll
    for (int o = 16; o; o >>= 1) s += __shfl_xor_sync(0xffffffffu, s, o);
    if (lane == 0) (which ? g_ssq : g_xsq)[w] = s;
}

// ---------------- main fused HMMA kernel: 256 thr, 8 warps of 64x64 ----------------
__global__ __launch_bounds__(256, 1)
void rbf_hmma_kernel(const float* __restrict__ alphas, const float* __restrict__ bias,
                     const float* __restrict__ sigma, float* __restrict__ out) {
    extern __shared__ char smem[];
    const uint32_t sb = smem_u32(smem);
    const int tid   = threadIdx.x;
    const int wid   = tid >> 5;
    const int lane  = tid & 31;
    const int warpM = wid >> 2;     // 0..1: rows warpM*64
    const int warpN = wid & 3;      // 0..3: cols warpN*64
    const int n0    = blockIdx.x * 128;

    float* smQ = (float*)(smem + OFF_Q);
    float* smA = (float*)(smem + OFF_A);
    float* smR = (float*)(smem + OFF_R);

    // Issue S chunk gidx (256 m-rows x 64 k) into ring buffer buf.
    // One thread per m-row, 8 x 16B each.
    auto issue_chunk = [&](int gidx, int buf) {
        const char* gp = (const char*)(g_Sb + (size_t)((gidx >> 3) * 256 + tid) * D_DIM
                                       + (gidx & 7) * 64);
        uint32_t sdst = sb + OFF_S + buf * 32768;
        #pragma unroll
        for (int i = 0; i < 8; i++) {
            uint32_t off = (uint32_t)(tid * 128 + i * 16);
            cp_async16(sdst + SW128(off), gp + i * 16);
        }
        CP_COMMIT();
    };

    issue_chunk(0, 0);   // get chunk 0 moving before the X fill

    // Tables resident in SMEM.
    for (int i = tid; i < M_COLS; i += 256) {
        smQ[i] = g_ssq[i];
        smA[i] = alphas[i];
    }
    // X block resident: 8 chunk-tiles (128 rows x 64 k bf16), SW128-swizzled.
    {
        const int row = tid >> 1, half = tid & 1;
        #pragma unroll
        for (int c = 0; c < 8; c++) {
            const uint4* p = reinterpret_cast<const uint4*>(
                g_Xb + (size_t)(n0 + row) * D_DIM + c * 64 + half * 32);
            #pragma unroll
            for (int i = 0; i < 4; i++) {
                uint32_t off = (uint32_t)(row * 128 + (half * 4 + i) * 16);
                *reinterpret_cast<uint4*>(smem + OFF_X + c * 16384 + SW128(off)) = p[i];
            }
        }
    }

    const float sg = sigma[0];
    const float inv2s2 = 1.0f / (2.0f * sg * sg);

    // Per-thread row norms for the 8 output rows this thread touches.
    float xq8[8];
    #pragma unroll
    for (int mt = 0; mt < 4; mt++)
        #pragma unroll
        for (int h = 0; h < 2; h++)
            xq8[mt * 2 + h] = g_xsq[n0 + warpM * 64 + mt * 16 + (lane >> 2) + 8 * h];

    float dec[8];
    #pragma unroll
    for (int i = 0; i < 8; i++) dec[i] = 0.f;

    for (int mtile = 0; mtile < 16; mtile++) {
        float acc[4][8][4];   // [mt][n8-tile][frag]
        #pragma unroll
        for (int mt = 0; mt < 4; mt++)
            #pragma unroll
            for (int n = 0; n < 8; n++)
                #pragma unroll
                for (int j = 0; j < 4; j++) acc[mt][n][j] = 0.f;

        for (int c = 0; c < 8; c++) {
            const int gidx = mtile * 8 + c;
            CP_WAIT(0);        // chunk gidx arrived
            __syncthreads();   // + all warps done reading the other buffer
            if (gidx + 1 < 128) issue_chunk(gidx + 1, (gidx + 1) & 1);

            const uint32_t xbase = sb + OFF_X + c * 16384;
            const uint32_t sbase = sb + OFF_S + (gidx & 1) * 32768;
            #pragma unroll
            for (int ks = 0; ks < 4; ks++) {
                uint32_t a[4][4];
                #pragma unroll
                for (int mt = 0; mt < 4; mt++) {
                    uint32_t off = (uint32_t)((warpM * 64 + mt * 16 + (lane & 15)) * 128
                                              + ks * 32 + (lane >> 4) * 16);
                    ldmatrix_x4(a[mt], xbase + SW128(off));
                }
                uint32_t b[4][4];
                #pragma unroll
                for (int ntp = 0; ntp < 4; ntp++) {
                    uint32_t off = (uint32_t)((warpN * 64 + ntp * 16 + (lane & 15)) * 128
                                              + ks * 32 + (lane >> 4) * 16);
                    ldmatrix_x4(b[ntp], sbase + SW128(off));
                }
                #pragma unroll
                for (int mt = 0; mt < 4; mt++)
                    #pragma unroll
                    for (int n = 0; n < 8; n++)
                        mma16816(acc[mt][n], a[mt],
                                 b[n >> 1][n & 1], b[n >> 1][(n & 1) + 2]);
            }
        }

        // Fused epilogue for this 256-column tile (overlaps in-flight prefetch).
        {
            const int mbase = mtile * 256 + warpN * 64;
            float sq16[16];
            #pragma unroll
            for (int n = 0; n < 8; n++)
                #pragma unroll
                for (int i = 0; i < 2; i++)
                    sq16[n * 2 + i] = smQ[mbase + n * 8 + 2 * (lane & 3) + i];

            float mx = -3.0e38f;
            #pragma unroll
            for (int mt = 0; mt < 4; mt++)
                #pragma unroll
                for (int n = 0; n < 8; n++)
                    #pragma unroll
                    for (int j = 0; j < 4; j++) {
                        float a = 2.0f * acc[mt][n][j] - xq8[mt * 2 + (j >> 1)] - sq16[n * 2 + (j & 1)];
                        mx = fmaxf(mx, a);
                    }
            // expf(x) == 0.0f exactly for x < -105 -> whole-tile skip is bit-exact.
            if (__any_sync(0xffffffffu, mx * inv2s2 > -105.0f)) {
                #pragma unroll
                for (int mt = 0; mt < 4; mt++)
                    #pragma unroll
                    for (int n = 0; n < 8; n++)
                        #pragma unroll
                        for (int j = 0; j < 4; j++) {
                            int m = mbase + n * 8 + 2 * (lane & 3) + (j & 1);
                            float arg = (2.0f * acc[mt][n][j] - xq8[mt * 2 + (j >> 1)]
                                         - sq16[n * 2 + (j & 1)]) * inv2s2;
                            dec[mt * 2 + (j >> 1)] = fmaf(smA[m], __expf(arg), dec[mt * 2 + (j >> 1)]);
                        }
            }
        }
    }

    // Deterministic reduction: quad shuffle (over columns), then cross-warpN via SMEM.
    #pragma unroll
    for (int i = 0; i < 8; i++) {
        dec[i] += __shfl_xor_sync(0xffffffffu, dec[i], 1);
        dec[i] += __shfl_xor_sync(0xffffffffu, dec[i], 2);
    }
    __syncthreads();
    if ((lane & 3) == 0) {
        #pragma unroll
        for (int i = 0; i < 8; i++) {
            int r = warpM * 64 + (i >> 1) * 16 + (lane >> 2) + 8 * (i & 1);
            smR[r * 4 + warpN] = dec[i];
        }
    }
    __syncthreads();
    if (tid < 128) {
        float s = smR[tid * 4] + smR[tid * 4 + 1] + smR[tid * 4 + 2] + smR[tid * 4 + 3] + bias[0];
        out[n0 + tid] = (s > 0.f) ? 1.f : ((s < 0.f) ? -1.f : 0.f);
    }
}

extern "C" void kernel_launch(void* const* d_in, const int* in_sizes, int n_in,
                              void* d_out, int out_size) {
    const float* X      = (const float*)d_in[0];
    const float* S      = (const float*)d_in[1];
    const float* alphas = (const float*)d_in[2];
    const float* bias   = (const float*)d_in[3];
    const float* sigma  = (const float*)d_in[4];
    float* out = (float*)d_out;

    prep_kernel<<<N_ROWS / 8, 256>>>(X, N_ROWS, 0);
    prep_kernel<<<M_COLS / 8, 256>>>(S, M_COLS, 1);

    cudaFuncSetAttribute(rbf_hmma_kernel,
                         cudaFuncAttributeMaxDynamicSharedMemorySize, SMEM_TOTAL);
    rbf_hmma_kernel<<<N_ROWS / 128, 256, SMEM_TOTAL>>>(alphas, bias, sigma, out);
}